// round 8
// baseline (speedup 1.0000x reference)
#include <cuda_runtime.h>

// Problem constants
#define BB     32
#define CC     16
#define IN_H   64
#define IN_W   64
#define OUT_H  60
#define OUT_W  60
#define KK     5
#define JT     6               // output cols per block
#define XCOLS  10              // JT + KK - 1
#define XSTR   36              // padded batch stride (32 + 4 floats)
#define NTHREADS 384           // 12 warps: 6 pixels x 2 batch-half warps

// Scratch: transposed input inT[c][y][x][b]  (batch contiguous)
__device__ float g_inT[CC * IN_H * IN_W * BB];

// ---------------------------------------------------------------------------
// Pre-kernel: in[b][c][y][x] -> inT[c][y][x][b]
// ---------------------------------------------------------------------------
__global__ void transpose_kernel(const float* __restrict__ in) {
    __shared__ float s[IN_W][BB + 1];
    const int c = blockIdx.x;
    const int y = blockIdx.y;
    const int t = threadIdx.x;          // 256 threads

    #pragma unroll
    for (int it = 0; it < 8; ++it) {
        int n = t + it * 256;           // 0..2047
        int x = n & 63;
        int b = n >> 6;
        s[x][b] = in[((b * CC + c) * IN_H + y) * IN_W + x];
    }
    __syncthreads();

    float* dst = g_inT + (size_t)(c * IN_H + y) * IN_W * BB;
    #pragma unroll
    for (int it = 0; it < 8; ++it) {
        int n = t + it * 256;
        int b = n & 31;
        int x = n >> 5;
        dst[x * BB + b] = s[x][b];
    }
}

// ---------------------------------------------------------------------------
// f32x2 helpers
// ---------------------------------------------------------------------------
__device__ __forceinline__ unsigned long long ffma2(
    unsigned long long a, unsigned long long b, unsigned long long c) {
    unsigned long long d;
    asm("fma.rn.f32x2 %0, %1, %2, %3;" : "=l"(d) : "l"(a), "l"(b), "l"(c));
    return d;
}
__device__ __forceinline__ unsigned long long pack2(float x, float y) {
    unsigned long long r;
    asm("mov.b64 %0, {%1, %2};" : "=l"(r) : "f"(x), "f"(y));
    return r;
}
__device__ __forceinline__ void unpack2(unsigned long long v, float& x, float& y) {
    asm("mov.b64 {%0, %1}, %2;" : "=f"(x), "=f"(y) : "l"(v));
}

// ---------------------------------------------------------------------------
// Main kernel.
//   grid (10, 60): block = (6-pixel j-tile, row i), 384 threads (12 warps).
//   warp w: pixel jl = w>>1, batch-half bh = w&1.
//   lane:  kop = lane>>2 (k_out pair), bq = lane&3 (4-batch group).
//   thread = 2 k_out x 4 batches = 4 f32x2 accumulators.
// Per (c,u,v): 1 LDS.128 (broadcast 8-way over kop), 1 LDG.64 weight
// (shared 4-way, 64B/warp contiguous), 4 FFMA2.
// ---------------------------------------------------------------------------
__global__ __launch_bounds__(NTHREADS, 3)
void lc_kernel(const float* __restrict__ wgt, float* __restrict__ out) {
    __shared__ float s[2][KK * XCOLS * XSTR];   // 2 x 1800 floats = 14.4KB

    const int j0   = blockIdx.x * JT;
    const int i    = blockIdx.y;
    const int tid  = threadIdx.x;
    const int warp = tid >> 5;
    const int lane = tid & 31;
    const int jl   = warp >> 1;                 // 0..5
    const int bh   = warp & 1;                  // batch half
    const int kop  = lane >> 2;                 // 0..7 (k_out pair)
    const int bq   = lane & 3;                  // 0..3 (4-batch group)
    const int j    = j0 + jl;

    // weight base as float2 for this (i,j) pixel and k_out pair
    const float2* wp = (const float2*)wgt + (size_t)(i * OUT_W + j) * 3200 + kop;

    unsigned long long acc0[2], acc1[2];
    acc0[0] = acc0[1] = acc1[0] = acc1[1] = 0ull;

    // ---- prologue: stage channel 0 (400 float4: bq8 = n&7, x, y) ----
    {
        int n = tid;                            // < 400 always for it=0? tid<384
        int b8 = n & 7, m = n >> 3;
        int x = m % XCOLS, y = m / XCOLS;
        *(float4*)&s[0][(y * XCOLS + x) * XSTR + 4 * b8] =
            *(const float4*)&g_inT[((size_t)(i + y) * IN_W + (j0 + x)) * BB + 4 * b8];
        int n2 = tid + NTHREADS;
        if (n2 < 400) {
            int b82 = n2 & 7, m2 = n2 >> 3;
            int x2 = m2 % XCOLS, y2 = m2 / XCOLS;
            *(float4*)&s[0][(y2 * XCOLS + x2) * XSTR + 4 * b82] =
                *(const float4*)&g_inT[((size_t)(i + y2) * IN_W + (j0 + x2)) * BB + 4 * b82];
        }
    }
    __syncthreads();

    // pre-load weights for (c=0, u=0)
    float2 wv[KK];
    #pragma unroll
    for (int v = 0; v < KK; ++v) wv[v] = wp[v * 8];

    int cur = 0;
    for (int c = 0; c < CC; ++c) {
        // ---- prefetch next channel's input tile into registers ----
        float4 pf0, pf1;
        bool havepf1 = false;
        int px0 = 0, py0 = 0, pb0 = 0, px1 = 0, py1 = 0, pb1 = 0;
        if (c + 1 < CC) {
            const float* src = g_inT + (size_t)(c + 1) * IN_H * IN_W * BB;
            int n = tid;
            pb0 = n & 7; int m = n >> 3; px0 = m % XCOLS; py0 = m / XCOLS;
            pf0 = *(const float4*)&src[((size_t)(i + py0) * IN_W + (j0 + px0)) * BB + 4 * pb0];
            int n2 = tid + NTHREADS;
            if (n2 < 400) {
                havepf1 = true;
                pb1 = n2 & 7; int m2 = n2 >> 3; px1 = m2 % XCOLS; py1 = m2 / XCOLS;
                pf1 = *(const float4*)&src[((size_t)(i + py1) * IN_W + (j0 + px1)) * BB + 4 * pb1];
            }
        }

        // ---- compute, with weight row pipelining ----
        const float* sb = s[cur] + jl * XSTR + bh * 16 + bq * 4;
        #pragma unroll
        for (int u = 0; u < KK; ++u) {
            // prefetch next weight row (next u, or next channel's u=0)
            float2 wn[KK];
            {
                const float2* wnp = wp + ((u < KK - 1) ? (u + 1) * 40
                                                       : (c < CC - 1 ? 200 : 0));
                #pragma unroll
                for (int v = 0; v < KK; ++v) wn[v] = wnp[v * 8];
            }
            #pragma unroll
            for (int v = 0; v < KK; ++v) {
                float4 xv = *(const float4*)(sb + (u * XCOLS + v) * XSTR);
                unsigned long long lo = pack2(xv.x, xv.y);
                unsigned long long hi = pack2(xv.z, xv.w);
                unsigned long long w0 = pack2(wv[v].x, wv[v].x);
                unsigned long long w1 = pack2(wv[v].y, wv[v].y);
                acc0[0] = ffma2(lo, w0, acc0[0]);
                acc0[1] = ffma2(hi, w0, acc0[1]);
                acc1[0] = ffma2(lo, w1, acc1[0]);
                acc1[1] = ffma2(hi, w1, acc1[1]);
            }
            #pragma unroll
            for (int v = 0; v < KK; ++v) wv[v] = wn[v];
        }
        wp += 200;   // next channel

        // ---- drain input prefetch into the other buffer ----
        if (c + 1 < CC) {
            *(float4*)&s[cur ^ 1][(py0 * XCOLS + px0) * XSTR + 4 * pb0] = pf0;
            if (havepf1)
                *(float4*)&s[cur ^ 1][(py1 * XCOLS + px1) * XSTR + 4 * pb1] = pf1;
        }
        __syncthreads();
        cur ^= 1;
    }

    // ---- epilogue: stage to smem, then coalesced global writes ----
    // so[(b*16 + ko)*6 + jl]
    float* so = &s[0][0];
    {
        const int base_b = bh * 16 + bq * 4;
        const int ko0 = 2 * kop;
        float a, b;
        unpack2(acc0[0], a, b);
        so[((base_b + 0) * CC + ko0) * JT + jl] = a;
        so[((base_b + 1) * CC + ko0) * JT + jl] = b;
        unpack2(acc0[1], a, b);
        so[((base_b + 2) * CC + ko0) * JT + jl] = a;
        so[((base_b + 3) * CC + ko0) * JT + jl] = b;
        unpack2(acc1[0], a, b);
        so[((base_b + 0) * CC + ko0 + 1) * JT + jl] = a;
        so[((base_b + 1) * CC + ko0 + 1) * JT + jl] = b;
        unpack2(acc1[1], a, b);
        so[((base_b + 2) * CC + ko0 + 1) * JT + jl] = a;
        so[((base_b + 3) * CC + ko0 + 1) * JT + jl] = b;
    }
    __syncthreads();

    // 3072 floats, 8 per thread: e = (b*16+ko)*6 + jj
    const size_t obase = (size_t)i * OUT_W + j0;
    #pragma unroll
    for (int it = 0; it < 8; ++it) {
        int e = tid + it * NTHREADS;
        int jj = e % JT;
        int rest = e / JT;                 // b*16 + ko
        out[(size_t)rest * (OUT_H * OUT_W) + obase + jj] = so[e];
    }
}

// ---------------------------------------------------------------------------
extern "C" void kernel_launch(void* const* d_in, const int* in_sizes, int n_in,
                              void* d_out, int out_size) {
    const float* in_spikes = (const float*)d_in[0];
    const float* weights   = (const float*)d_in[1];
    float* out             = (float*)d_out;

    transpose_kernel<<<dim3(CC, IN_H), 256>>>(in_spikes);
    lc_kernel<<<dim3(OUT_W / JT, OUT_H), NTHREADS>>>(weights, out);
}

// round 9
// speedup vs baseline: 1.2935x; 1.2935x over previous
#include <cuda_runtime.h>

#define BB     32
#define CC     16
#define IN_H   64
#define IN_W   64
#define OUT_H  60
#define OUT_W  60
#define KK     5
#define JT     10
#define XCOLS  14
#define XSTR   36
#define NTHREADS 320
#define TILE_F  2520
#define SMEM_F  5120           // max(2*TILE_F, 32*16*JT)
#define CSTRIDE ((size_t)IN_H * IN_W * BB)

typedef unsigned long long ull;

__device__ float g_inT[CC * IN_H * IN_W * BB];

__global__ void transpose_kernel(const float* __restrict__ in) {
    __shared__ float s[IN_W][BB + 1];
    const int c = blockIdx.x;
    const int y = blockIdx.y;
    const int t = threadIdx.x;

    #pragma unroll
    for (int it = 0; it < 8; ++it) {
        int n = t + it * 256;
        int x = n & 63;
        int b = n >> 6;
        s[x][b] = in[((b * CC + c) * IN_H + y) * IN_W + x];
    }
    __syncthreads();

    float* dst = g_inT + (size_t)(c * IN_H + y) * IN_W * BB;
    #pragma unroll
    for (int it = 0; it < 8; ++it) {
        int n = t + it * 256;
        int b = n & 31;
        int x = n >> 5;
        dst[x * BB + b] = s[x][b];
    }
}

__device__ __forceinline__ ull ffma2(ull a, ull b, ull c) {
    ull d;
    asm("fma.rn.f32x2 %0, %1, %2, %3;" : "=l"(d) : "l"(a), "l"(b), "l"(c));
    return d;
}
__device__ __forceinline__ ull pack2(float x, float y) {
    ull r;
    asm("mov.b64 %0, {%1, %2};" : "=l"(r) : "f"(x), "f"(y));
    return r;
}
__device__ __forceinline__ void unpack2(ull v, float& x, float& y) {
    asm("mov.b64 {%0, %1}, %2;" : "=f"(x), "=f"(y) : "l"(v));
}

__global__ __launch_bounds__(NTHREADS, 2)
void lc_kernel(const float* __restrict__ wgt, float* __restrict__ out) {
    __shared__ float smem[SMEM_F];

    const int j0   = blockIdx.x * JT;
    const int i    = blockIdx.y;
    const int tid  = threadIdx.x;
    const int jl   = tid >> 5;
    const int lane = tid & 31;
    const int bq   = lane >> 2;
    const int kh   = (lane >> 1) & 1;
    const int pg   = lane & 1;
    const int j    = j0 + jl;

    int off2[13];
    #pragma unroll
    for (int k = 0; k < 13; ++k) {
        int p = pg * 13 + k;
        if (p > 24) p = 24;                 // dummy slot (weight forced 0)
        int u = p / 5, v = p % 5;
        off2[k] = (u * XCOLS + v + jl) * XSTR + bq * 4;
    }

    const int cla = tid >> 3, b8a = tid & 7;
    const int xa = cla % XCOLS, ya = cla / XCOLS;
    const int sia = cla * XSTR + b8a * 4;
    const size_t gia = ((size_t)(i + ya) * IN_W + (j0 + xa)) * BB + b8a * 4;
    const int n2 = tid + NTHREADS;
    const bool hb = n2 < 560;
    const int clb = n2 >> 3, b8b = n2 & 7;
    const int xb = clb % XCOLS, yb = clb / XCOLS;
    const int sib = clb * XSTR + b8b * 4;
    const size_t gib = ((size_t)(i + yb) * IN_W + (j0 + xb)) * BB + b8b * 4;

    *(float4*)&smem[sia] = *(const float4*)&g_inT[gia];
    if (hb) *(float4*)&smem[sib] = *(const float4*)&g_inT[gib];
    __syncthreads();

    const float* wtc = wgt + ((size_t)(i * OUT_W + j) * CC * 25 + pg * 13) * CC + kh * 8;

    ull acc[4][4];
    #pragma unroll
    for (int kp = 0; kp < 4; ++kp)
        #pragma unroll
        for (int b2 = 0; b2 < 4; ++b2) acc[kp][b2] = 0ull;

    float4 wA = *(const float4*)wtc;
    float4 wB = *(const float4*)(wtc + 4);

    int cur = 0;
    for (int c = 0; c < CC; ++c) {
        float4 pfa, pfb;
        if (c + 1 < CC) {
            const size_t co = (size_t)(c + 1) * CSTRIDE;
            pfa = *(const float4*)&g_inT[gia + co];
            if (hb) pfb = *(const float4*)&g_inT[gib + co];
        }

        const float* sb = smem + cur * TILE_F;
        #pragma unroll
        for (int k = 0; k < 13; ++k) {
            float4 nA, nB;
            {
                const float* np = (k < 12) ? (wtc + (k + 1) * 16) : (wtc + 400);
                bool nv = (k < 11) ? true
                         : (k == 11 ? (pg == 0) : (c < CC - 1));
                if (nv) {
                    nA = *(const float4*)np;
                    nB = *(const float4*)(np + 4);
                } else {
                    nA = make_float4(0.f, 0.f, 0.f, 0.f);
                    nB = nA;
                }
            }

            float4 xv = *(const float4*)(sb + off2[k]);
            ull xs[4];
            xs[0] = pack2(xv.x, xv.x);
            xs[1] = pack2(xv.y, xv.y);
            xs[2] = pack2(xv.z, xv.z);
            xs[3] = pack2(xv.w, xv.w);
            ull ws[4];
            ws[0] = pack2(wA.x, wA.y);
            ws[1] = pack2(wA.z, wA.w);
            ws[2] = pack2(wB.x, wB.y);
            ws[3] = pack2(wB.z, wB.w);
            #pragma unroll
            for (int kp = 0; kp < 4; ++kp)
                #pragma unroll
                for (int b2 = 0; b2 < 4; ++b2)
                    acc[kp][b2] = ffma2(xs[b2], ws[kp], acc[kp][b2]);

            wA = nA; wB = nB;
        }
        wtc += 400;

        if (c + 1 < CC) {
            float* db = smem + (cur ^ 1) * TILE_F;
            *(float4*)&db[sia] = pfa;
            if (hb) *(float4*)&db[sib] = pfb;
        }
        __syncthreads();
        cur ^= 1;
    }

    // epilogue: reduce pg pairs, stage, coalesced writes
    float* so = smem;
    #pragma unroll
    for (int kp = 0; kp < 4; ++kp) {
        #pragma unroll
        for (int b2 = 0; b2 < 4; ++b2) {
            float lo, hi;
            unpack2(acc[kp][b2], lo, hi);
            lo += __shfl_xor_sync(0xffffffffu, lo, 1);
            hi += __shfl_xor_sync(0xffffffffu, hi, 1);
            if ((kp >> 1) == pg) {
                int b  = bq * 4 + b2;
                int ko = kh * 8 + kp * 2;
                so[(b * CC + ko    ) * JT + jl] = lo;
                so[(b * CC + ko + 1) * JT + jl] = hi;
            }
        }
    }
    __syncthreads();

    const size_t obase = (size_t)i * OUT_W + j0;
    #pragma unroll
    for (int it = 0; it < 16; ++it) {
        int e = tid + it * NTHREADS;
        int jj = e % JT;
        int rest = e / JT;
        out[(size_t)rest * (OUT_H * OUT_W) + obase + jj] = so[e];
    }
}

extern "C" void kernel_launch(void* const* d_in, const int* in_sizes, int n_in,
                              void* d_out, int out_size) {
    const float* in_spikes = (const float*)d_in[0];
    const float* weights   = (const float*)d_in[1];
    float* out             = (float*)d_out;

    transpose_kernel<<<dim3(CC, IN_H), 256>>>(in_spikes);
    lc_kernel<<<dim3(OUT_W / JT, OUT_H), NTHREADS>>>(weights, out);
}

// round 10
// speedup vs baseline: 2.2182x; 1.7149x over previous
#include <cuda_runtime.h>

// Problem constants
#define BB     32
#define CC     16
#define IN_H   64
#define IN_W   64
#define OUT_H  60
#define OUT_W  60
#define KK     5
#define JT     10              // pixels (warps) per block
#define NTHREADS 320           // 10 warps
#define CSTRIDE ((size_t)IN_H * IN_W * BB)

typedef unsigned long long ull;

// Scratch: transposed input inT[c][y][x][b]  (batch contiguous 128B lines)
__device__ float g_inT[CC * IN_H * IN_W * BB];

// ---------------------------------------------------------------------------
// Pre-kernel: in[b][c][y][x] -> inT[c][y][x][b]
// ---------------------------------------------------------------------------
__global__ void transpose_kernel(const float* __restrict__ in) {
    __shared__ float s[IN_W][BB + 1];
    const int c = blockIdx.x;
    const int y = blockIdx.y;
    const int t = threadIdx.x;          // 256 threads

    #pragma unroll
    for (int it = 0; it < 8; ++it) {
        int n = t + it * 256;           // 0..2047
        int x = n & 63;
        int b = n >> 6;
        s[x][b] = in[((b * CC + c) * IN_H + y) * IN_W + x];
    }
    __syncthreads();

    float* dst = g_inT + (size_t)(c * IN_H + y) * IN_W * BB;
    #pragma unroll
    for (int it = 0; it < 8; ++it) {
        int n = t + it * 256;
        int b = n & 31;
        int x = n >> 5;
        dst[x * BB + b] = s[x][b];
    }
}

// ---------------------------------------------------------------------------
// f32x2 helpers
// ---------------------------------------------------------------------------
__device__ __forceinline__ ull ffma2(ull a, ull b, ull c) {
    ull d;
    asm("fma.rn.f32x2 %0, %1, %2, %3;" : "=l"(d) : "l"(a), "l"(b), "l"(c));
    return d;
}
__device__ __forceinline__ ull pack2(float x, float y) {
    ull r;
    asm("mov.b64 %0, {%1, %2};" : "=l"(r) : "f"(x), "f"(y));
    return r;
}
__device__ __forceinline__ void unpack2(ull v, float& x, float& y) {
    asm("mov.b64 {%0, %1}, %2;" : "=f"(x), "=f"(y) : "l"(v));
}

// ---------------------------------------------------------------------------
// Main kernel.
//   grid (6, 60): block = 10-pixel j-tile on row i, 320 threads (10 warps).
//   warp = one output pixel. lane = bq (batch quad, 0-7) x ks (ko quad, 0-3).
//   thread = 4 batches x 4 k_out = 8 f32x2 accumulators.
// Per (c,u,v): 1 input LDG.128 (one 128B line, 4-way dedup),
//              1 weight LDG.128 (64B contiguous, 8-way dedup), 8 FFMA2.
// No shared memory, no barriers until the epilogue stage.
// ---------------------------------------------------------------------------
__global__ __launch_bounds__(NTHREADS, 3)
void lc_kernel(const float* __restrict__ wgt, float* __restrict__ out) {
    __shared__ float so[BB * CC * JT];   // 5120 floats, epilogue staging only

    const int j0   = blockIdx.x * JT;
    const int i    = blockIdx.y;
    const int tid  = threadIdx.x;
    const int jl   = tid >> 5;                  // warp = pixel 0..9
    const int lane = tid & 31;
    const int bq   = lane >> 2;                 // batch quad 0..7
    const int ks   = lane & 3;                  // ko quad 0..3
    const int j    = j0 + jl;

    // input base: g_inT[c=0][i][j][bq*4], advance by (u*IN_W+v)*BB and CSTRIDE
    const float* ip = g_inT + ((size_t)i * IN_W + j) * BB + bq * 4;
    // weight base: wgt[(i*60+j)*6400 + c*400 + (u*5+v)*16 + ks*4]
    const float* wp = wgt + (size_t)(i * OUT_W + j) * (CC * KK * KK * CC) + ks * 4;

    ull acc[4][2];
    #pragma unroll
    for (int t = 0; t < 4; ++t) { acc[t][0] = 0ull; acc[t][1] = 0ull; }

    for (int c = 0; c < CC; ++c) {
        #pragma unroll
        for (int u = 0; u < KK; ++u) {
            #pragma unroll
            for (int v = 0; v < KK; ++v) {
                float4 xv = *(const float4*)(ip + (u * IN_W + v) * BB);
                float4 wv = *(const float4*)(wp + (u * KK + v) * CC);
                ull xlo = pack2(xv.x, xv.y);
                ull xhi = pack2(xv.z, xv.w);
                ull w0 = pack2(wv.x, wv.x);
                ull w1 = pack2(wv.y, wv.y);
                ull w2 = pack2(wv.z, wv.z);
                ull w3 = pack2(wv.w, wv.w);
                acc[0][0] = ffma2(xlo, w0, acc[0][0]);
                acc[0][1] = ffma2(xhi, w0, acc[0][1]);
                acc[1][0] = ffma2(xlo, w1, acc[1][0]);
                acc[1][1] = ffma2(xhi, w1, acc[1][1]);
                acc[2][0] = ffma2(xlo, w2, acc[2][0]);
                acc[2][1] = ffma2(xhi, w2, acc[2][1]);
                acc[3][0] = ffma2(xlo, w3, acc[3][0]);
                acc[3][1] = ffma2(xhi, w3, acc[3][1]);
            }
        }
        ip += CSTRIDE;            // next input channel
        wp += KK * KK * CC;       // next weight channel (400 floats)
    }

    // ---- epilogue: stage to smem, then coalesced global writes ----
    // so[(b*16 + ko)*JT + jl]
    #pragma unroll
    for (int t = 0; t < 4; ++t) {
        const int ko = ks * 4 + t;
        float a, b;
        unpack2(acc[t][0], a, b);
        so[((bq * 4 + 0) * CC + ko) * JT + jl] = a;
        so[((bq * 4 + 1) * CC + ko) * JT + jl] = b;
        unpack2(acc[t][1], a, b);
        so[((bq * 4 + 2) * CC + ko) * JT + jl] = a;
        so[((bq * 4 + 3) * CC + ko) * JT + jl] = b;
    }
    __syncthreads();

    // 5120 floats, 16 per thread: e = (b*16+ko)*JT + jj -> 40B coalesced runs
    const size_t obase = (size_t)i * OUT_W + j0;
    #pragma unroll
    for (int it = 0; it < 16; ++it) {
        int e = tid + it * NTHREADS;
        int jj = e % JT;
        int rest = e / JT;                 // b*16 + ko
        out[(size_t)rest * (OUT_H * OUT_W) + obase + jj] = so[e];
    }
}

// ---------------------------------------------------------------------------
extern "C" void kernel_launch(void* const* d_in, const int* in_sizes, int n_in,
                              void* d_out, int out_size) {
    const float* in_spikes = (const float*)d_in[0];
    const float* weights   = (const float*)d_in[1];
    float* out             = (float*)d_out;

    transpose_kernel<<<dim3(CC, IN_H), 256>>>(in_spikes);
    lc_kernel<<<dim3(OUT_W / JT, OUT_H), NTHREADS>>>(weights, out);
}